// round 12
// baseline (speedup 1.0000x reference)
#include <cuda_runtime.h>
#include <cuda_bf16.h>
#include <cstdint>

#define NCLS 10
#define DIM  128
#define BATCH 4                         // rows per warp per iteration
#define ACC_WARPS 4
#define ACC_THREADS 128
#define ACC_GRID 1184                   // 8 blocks/SM * 148 SMs
#define ACC_TOTAL_WARPS (ACC_GRID * ACC_WARPS)   // 4736

#define CNT_GRID 296
#define CNT_THREADS 256

#define WSLOT 1600                      // floats per warp copy: 1280 sum + 320 q
#define NFINAL (NCLS * DIM + NCLS)      // 1280 sums + 10 class-S2

// Allocation-free scratch. g_final zeroed by the zero+count kernel each launch
// (deterministic replay); g_pcnt is overwritten (no zeroing needed).
__device__ float        g_final[NFINAL];
__device__ unsigned int g_pcnt[CNT_GRID * NCLS];

// ---------------------------------------------------------------------------
// Kernel 1: zero g_final + per-block label histogram (counts leave the hot
// accum loop entirely). Per-warp smem counters -> per-block partial counts.
// ---------------------------------------------------------------------------
__global__ __launch_bounds__(CNT_THREADS)
void CLIR_zero_count_kernel(const int* __restrict__ t, int N) {
    __shared__ unsigned int hc[CNT_THREADS / 32][NCLS];
    const int tid  = threadIdx.x;
    const int warp = tid >> 5;

    // Zero g_final (grid-strided across blocks)
    for (int i = blockIdx.x * CNT_THREADS + tid; i < NFINAL;
         i += CNT_GRID * CNT_THREADS)
        g_final[i] = 0.0f;

    if (tid < NCLS * (CNT_THREADS / 32)) hc[tid / NCLS][tid % NCLS] = 0u;
    __syncthreads();

    const int N4 = N >> 2;
    const int4* t4 = (const int4*)t;
    for (int i = blockIdx.x * CNT_THREADS + tid; i < N4;
         i += CNT_GRID * CNT_THREADS) {
        const int4 l = t4[i];
        atomicAdd(&hc[warp][l.x], 1u);
        atomicAdd(&hc[warp][l.y], 1u);
        atomicAdd(&hc[warp][l.z], 1u);
        atomicAdd(&hc[warp][l.w], 1u);
    }
    // tail (N not multiple of 4): first block only
    if (blockIdx.x == 0 && tid < (N & 3))
        atomicAdd(&hc[0][t[N4 * 4 + tid]], 1u);
    __syncthreads();

    if (tid < NCLS) {
        unsigned s = 0;
        #pragma unroll
        for (int w = 0; w < CNT_THREADS / 32; w++) s += hc[w][tid];
        g_pcnt[blockIdx.x * NCLS + tid] = s;    // overwrite: deterministic
    }
}

// ---------------------------------------------------------------------------
// Kernel 2: streaming accumulation. Per-warp PRIVATE smem copy of the
// per-class sums (lane l owns features 4l..4l+3) plus a per-(class,lane)
// scalar partial of the sum-of-squares. Branch-free: class indexes smem.
// ~15 instr + 1280 B smem traffic per 512 B row; 32 warps/SM.
// ---------------------------------------------------------------------------
#define ROW(v, c) do {                                                \
    float4* ps = (float4*)(ws + (c) * DIM + lane * 4);                \
    float4 a = *ps;                                                   \
    a.x += (v).x; a.y += (v).y; a.z += (v).z; a.w += (v).w;           \
    *ps = a;                                                          \
    float d = fmaf((v).y,(v).y,(v).x*(v).x)                           \
            + fmaf((v).w,(v).w,(v).z*(v).z);                          \
    wq[(c) * 32 + lane] += d;                                         \
} while (0)

__global__ __launch_bounds__(ACC_THREADS, 8)
void CLIR_accum_kernel(const float* __restrict__ x,
                       const int*   __restrict__ t,
                       int N) {
    __shared__ float acc[ACC_WARPS][WSLOT];   // 25.6 KB

    const int tid  = threadIdx.x;
    const int lane = tid & 31;
    const int warp = tid >> 5;
    const int gw   = blockIdx.x * ACC_WARPS + warp;

    for (int i = tid; i < ACC_WARPS * WSLOT; i += ACC_THREADS)
        (&acc[0][0])[i] = 0.0f;
    __syncthreads();

    float* ws = acc[warp];                    // sums: [c*128 + feat]
    float* wq = acc[warp] + NCLS * DIM;       // q:    [c*32 + lane]
    const float4* __restrict__ x4 = (const float4*)x;

    for (int base = gw * BATCH; base < N; base += ACC_TOTAL_WARPS * BATCH) {
        if (base + BATCH <= N) {
            const int4 lab = __ldg((const int4*)(t + base));
            const size_t r = (size_t)base * (DIM / 4) + lane;
            const float4 v0 = x4[r + 0 * 32];
            const float4 v1 = x4[r + 1 * 32];
            const float4 v2 = x4[r + 2 * 32];
            const float4 v3 = x4[r + 3 * 32];
            ROW(v0, lab.x);
            ROW(v1, lab.y);
            ROW(v2, lab.z);
            ROW(v3, lab.w);
        } else {
            for (int j = 0; base + j < N; j++) {
                const int c = __ldg(t + base + j);
                const float4 v = x4[(size_t)(base + j) * (DIM / 4) + lane];
                ROW(v, c);
            }
        }
    }
    __syncthreads();

    // Fold 4 warp copies -> spread global float atomics (REDG).
    for (int i = tid; i < NCLS * DIM; i += ACC_THREADS) {
        const float v = acc[0][i] + acc[1][i] + acc[2][i] + acc[3][i];
        atomicAdd(&g_final[i], v);
    }
    for (int i = tid; i < NCLS * 32; i += ACC_THREADS) {
        const float v = acc[0][NCLS * DIM + i] + acc[1][NCLS * DIM + i]
                      + acc[2][NCLS * DIM + i] + acc[3][NCLS * DIM + i];
        atomicAdd(&g_final[NCLS * DIM + (i >> 5)], v);
    }
}
#undef ROW

// ---------------------------------------------------------------------------
// penalty = (1/C) * Σ_c [ S2_c/(n_c-1) - Σ_d sum[c][d]^2 / (n_c (n_c-1)) ]
// ---------------------------------------------------------------------------
__global__ void CLIR_finalize_kernel(float* __restrict__ out) {
    __shared__ unsigned int ic[NCLS];
    __shared__ float scnt[NCLS];
    const int d = threadIdx.x;   // 128 threads
    if (d < NCLS) ic[d] = 0u;
    __syncthreads();
    for (int j = d; j < CNT_GRID * NCLS; j += 128)
        atomicAdd(&ic[j % NCLS], g_pcnt[j]);
    __syncthreads();
    if (d < NCLS) scnt[d] = (float)ic[d];
    __syncthreads();

    float p = 0.0f;
    #pragma unroll
    for (int c = 0; c < NCLS; c++) {
        const float n = scnt[c];
        const float s = g_final[c * DIM + d];
        p += (s * s) / (n * (n - 1.0f));
    }
    #pragma unroll
    for (int o = 16; o > 0; o >>= 1)
        p += __shfl_xor_sync(0xFFFFFFFFu, p, o);
    __shared__ float wr[4];
    if ((d & 31) == 0) wr[d >> 5] = p;
    __syncthreads();
    if (d == 0) {
        float tr = 0.0f;
        #pragma unroll
        for (int c = 0; c < NCLS; c++)
            tr += g_final[NCLS * DIM + c] / (scnt[c] - 1.0f);
        out[0] = (tr - (wr[0] + wr[1] + wr[2] + wr[3])) * (1.0f / (float)NCLS);
    }
}

extern "C" void kernel_launch(void* const* d_in, const int* in_sizes, int n_in,
                              void* d_out, int out_size) {
    const float* x = (const float*)d_in[0];
    const int*   t = (const int*)d_in[1];
    const int N = in_sizes[1];

    CLIR_zero_count_kernel<<<CNT_GRID, CNT_THREADS>>>(t, N);
    CLIR_accum_kernel<<<ACC_GRID, ACC_THREADS>>>(x, t, N);
    CLIR_finalize_kernel<<<1, DIM>>>((float*)d_out);
}

// round 13
// speedup vs baseline: 2.4969x; 2.4969x over previous
#include <cuda_runtime.h>
#include <cuda_bf16.h>
#include <cstdint>

#define NCLS 10
#define DIM  128
#define MAXN 1048576

// histogram / scatter chunking: 248 blocks x 256 thr, 4 int4 per thread
#define CHB 248
#define CHT 256
#define CHUNKS 8                     // 248 = 8 * 31 for the two-level scan
#define CHUNK_B 31

// accum kernel
#define A4_THREADS 256
#define A4_BLOCKS  444               // 3 blocks/SM * 148 SMs
#define A4_TW      (A4_BLOCKS * 8)   // 3552 warps

#define NFINAL (NCLS * DIM + NCLS)   // 1280 sums + 10 class sum-of-squares

// Allocation-free scratch. g_final zeroed by k1 each launch; everything else
// is overwritten every launch (deterministic replay of the graph).
__device__ float        g_final[NFINAL];
__device__ unsigned int g_bhist[CHB * NCLS];
__device__ unsigned int g_boff [CHB * NCLS];
__device__ unsigned int g_classoff[NCLS + 1];
__device__ int          g_idx[MAXN];

// ---------------------------------------------------------------------------
// K1: zero g_final + per-block label histogram.
// Block b owns int4 indices { b*1024 + k*256 + tid : k<4 } (identical set in K3).
// ---------------------------------------------------------------------------
__global__ __launch_bounds__(CHT)
void CLIR_k1_zero_hist(const int* __restrict__ t, int N) {
    __shared__ unsigned int hc[CHT / 32][NCLS];
    const int tid  = threadIdx.x;
    const int warp = tid >> 5;
    const int b    = blockIdx.x;

    for (int i = b * CHT + tid; i < NFINAL; i += CHB * CHT)
        g_final[i] = 0.0f;
    if (tid < NCLS * (CHT / 32)) hc[tid / NCLS][tid % NCLS] = 0u;
    __syncthreads();

    const int N4 = N >> 2;
    const int4* t4 = (const int4*)t;
    int4 l[4]; int ok[4];
    #pragma unroll
    for (int k = 0; k < 4; k++) {
        const int i = b * 1024 + k * 256 + tid;
        ok[k] = (i < N4);
        if (ok[k]) l[k] = __ldg(&t4[i]);
    }
    #pragma unroll
    for (int k = 0; k < 4; k++) {
        if (ok[k]) {
            atomicAdd(&hc[warp][l[k].x], 1u);
            atomicAdd(&hc[warp][l[k].y], 1u);
            atomicAdd(&hc[warp][l[k].z], 1u);
            atomicAdd(&hc[warp][l[k].w], 1u);
        }
    }
    if (b == 0 && tid < (N & 3))
        atomicAdd(&hc[0][__ldg(t + (N4 << 2) + tid)], 1u);
    __syncthreads();

    if (tid < NCLS) {
        unsigned s = 0;
        #pragma unroll
        for (int w = 0; w < CHT / 32; w++) s += hc[w][tid];
        g_bhist[b * NCLS + tid] = s;
    }
}

// ---------------------------------------------------------------------------
// K2: one block. classoff[] (global class boundaries) + per-block class bases.
// Two-level prefix: (class, chunk-of-31-blocks) by 80 threads.
// ---------------------------------------------------------------------------
__global__ __launch_bounds__(128)
void CLIR_k2_scan() {
    __shared__ unsigned int sh[CHB * NCLS];          // 2480
    __shared__ unsigned int part[NCLS][CHUNKS];
    __shared__ unsigned int ctot[NCLS];
    __shared__ unsigned int coff[NCLS + 1];
    const int tid = threadIdx.x;

    for (int i = tid; i < CHB * NCLS; i += 128) sh[i] = g_bhist[i];
    __syncthreads();

    if (tid < NCLS * CHUNKS) {
        const int c = tid / CHUNKS, ch = tid % CHUNKS;
        unsigned s = 0;
        for (int j = 0; j < CHUNK_B; j++) s += sh[(ch * CHUNK_B + j) * NCLS + c];
        part[c][ch] = s;
    }
    __syncthreads();
    if (tid < NCLS) {
        unsigned s = 0;
        #pragma unroll
        for (int ch = 0; ch < CHUNKS; ch++) {
            const unsigned v = part[tid][ch];
            part[tid][ch] = s;
            s += v;
        }
        ctot[tid] = s;
    }
    __syncthreads();
    if (tid == 0) {
        unsigned s = 0;
        #pragma unroll
        for (int c = 0; c < NCLS; c++) { coff[c] = s; s += ctot[c]; }
        coff[NCLS] = s;
    }
    __syncthreads();
    if (tid < NCLS * CHUNKS) {
        const int c = tid / CHUNKS, ch = tid % CHUNKS;
        unsigned run = coff[c] + part[c][ch];
        for (int j = 0; j < CHUNK_B; j++) {
            const int b = ch * CHUNK_B + j;
            g_boff[b * NCLS + c] = run;
            run += sh[b * NCLS + c];
        }
    }
    if (tid < NCLS + 1) g_classoff[tid] = coff[tid];
}

// ---------------------------------------------------------------------------
// K3: scatter row indices class-contiguously into g_idx (same chunking as K1).
// ---------------------------------------------------------------------------
__global__ __launch_bounds__(CHT)
void CLIR_k3_scatter(const int* __restrict__ t, int N) {
    __shared__ unsigned int lcnt[NCLS];
    __shared__ unsigned int base[NCLS];
    const int tid = threadIdx.x;
    const int b   = blockIdx.x;

    if (tid < NCLS) { lcnt[tid] = 0u; base[tid] = g_boff[b * NCLS + tid]; }
    __syncthreads();

    const int N4 = N >> 2;
    const int4* t4 = (const int4*)t;
    #pragma unroll
    for (int k = 0; k < 4; k++) {
        const int i = b * 1024 + k * 256 + tid;
        if (i < N4) {
            const int4 l = __ldg(&t4[i]);
            const int row = i << 2;
            unsigned p;
            p = atomicAdd(&lcnt[l.x], 1u); g_idx[base[l.x] + p] = row + 0;
            p = atomicAdd(&lcnt[l.y], 1u); g_idx[base[l.y] + p] = row + 1;
            p = atomicAdd(&lcnt[l.z], 1u); g_idx[base[l.z] + p] = row + 2;
            p = atomicAdd(&lcnt[l.w], 1u); g_idx[base[l.w] + p] = row + 3;
        }
    }
    if (b == 0 && tid < (N & 3)) {
        const int row = (N4 << 2) + tid;
        const int c = __ldg(t + row);
        const unsigned p = atomicAdd(&lcnt[c], 1u);
        g_idx[base[c] + p] = row;
    }
}

// ---------------------------------------------------------------------------
// K4: streaming accum over class-sorted g_idx. One uniform class per warp
// position -> ONE float4 sum + one scalar q in registers (~60 regs total).
// 8-row gather batches (4 KB in flight/warp), 24 warps/SM = 96 KB in flight.
// ---------------------------------------------------------------------------
#define UPDA(v) do {                                                     \
    acc.x += (v).x; acc.y += (v).y; acc.z += (v).z; acc.w += (v).w;      \
    q += fmaf((v).y,(v).y,(v).x*(v).x)                                   \
       + fmaf((v).w,(v).w,(v).z*(v).z);                                  \
} while (0)

__device__ __forceinline__ void flush_acc(int c, int lane, float4 acc, float q) {
    atomicAdd(&g_final[c * DIM + lane * 4 + 0], acc.x);
    atomicAdd(&g_final[c * DIM + lane * 4 + 1], acc.y);
    atomicAdd(&g_final[c * DIM + lane * 4 + 2], acc.z);
    atomicAdd(&g_final[c * DIM + lane * 4 + 3], acc.w);
    atomicAdd(&g_final[NCLS * DIM + c], q);
}

__global__ __launch_bounds__(A4_THREADS, 3)
void CLIR_k4_accum(const float* __restrict__ x, int N) {
    __shared__ unsigned int co[NCLS + 1];
    const int tid  = threadIdx.x;
    const int lane = tid & 31;
    if (tid < NCLS + 1) co[tid] = g_classoff[tid];
    __syncthreads();

    const int gw = blockIdx.x * 8 + (tid >> 5);
    const unsigned slice = (unsigned)((((N + A4_TW - 1) / A4_TW) + 7) & ~7);
    const unsigned p0   = gw * slice;
    const unsigned pend = min(p0 + slice, (unsigned)N);
    if (p0 >= pend) return;

    int c = 0;
    while (c < NCLS - 1 && p0 >= co[c + 1]) c++;
    unsigned nb = co[c + 1];

    float4 acc = {0.f, 0.f, 0.f, 0.f};
    float  q   = 0.f;
    const float4* __restrict__ x4 = (const float4*)x;

    for (unsigned P = p0; P < pend; P += 8) {
        if (P + 8 <= pend && P + 8 <= nb) {
            const int4 ia = __ldg((const int4*)(g_idx + P));
            const int4 ib = __ldg((const int4*)(g_idx + P + 4));
            const float4 v0 = x4[(size_t)ia.x * 32 + lane];
            const float4 v1 = x4[(size_t)ia.y * 32 + lane];
            const float4 v2 = x4[(size_t)ia.z * 32 + lane];
            const float4 v3 = x4[(size_t)ia.w * 32 + lane];
            const float4 v4 = x4[(size_t)ib.x * 32 + lane];
            const float4 v5 = x4[(size_t)ib.y * 32 + lane];
            const float4 v6 = x4[(size_t)ib.z * 32 + lane];
            const float4 v7 = x4[(size_t)ib.w * 32 + lane];
            UPDA(v0); UPDA(v1); UPDA(v2); UPDA(v3);
            UPDA(v4); UPDA(v5); UPDA(v6); UPDA(v7);
        } else {
            for (unsigned j = 0; j < 8 && P + j < pend; j++) {
                if (P + j >= nb) {               // class boundary: flush, advance
                    flush_acc(c, lane, acc, q);
                    acc = make_float4(0.f, 0.f, 0.f, 0.f);
                    q = 0.f;
                    do { c++; } while (P + j >= co[c + 1]);
                    nb = co[c + 1];
                }
                const int idx = __ldg(g_idx + P + j);
                const float4 v = x4[(size_t)idx * 32 + lane];
                UPDA(v);
            }
        }
    }
    flush_acc(c, lane, acc, q);
}

// ---------------------------------------------------------------------------
// K5: penalty = (1/C) * Σ_c [ q_c/(n_c-1) - Σ_d sum[c][d]^2 / (n_c (n_c-1)) ]
// ---------------------------------------------------------------------------
__global__ void CLIR_k5_finalize(float* __restrict__ out) {
    __shared__ float scnt[NCLS];
    const int d = threadIdx.x;   // 128 threads
    if (d < NCLS) scnt[d] = (float)(g_classoff[d + 1] - g_classoff[d]);
    __syncthreads();

    float p = 0.0f;
    #pragma unroll
    for (int c = 0; c < NCLS; c++) {
        const float n = scnt[c];
        const float s = g_final[c * DIM + d];
        p += (s * s) / (n * (n - 1.0f));
    }
    #pragma unroll
    for (int o = 16; o > 0; o >>= 1)
        p += __shfl_xor_sync(0xFFFFFFFFu, p, o);
    __shared__ float wr[4];
    if ((d & 31) == 0) wr[d >> 5] = p;
    __syncthreads();
    if (d == 0) {
        float tr = 0.0f;
        #pragma unroll
        for (int c = 0; c < NCLS; c++)
            tr += g_final[NCLS * DIM + c] / (scnt[c] - 1.0f);
        out[0] = (tr - (wr[0] + wr[1] + wr[2] + wr[3])) * (1.0f / (float)NCLS);
    }
}

extern "C" void kernel_launch(void* const* d_in, const int* in_sizes, int n_in,
                              void* d_out, int out_size) {
    const float* x = (const float*)d_in[0];
    const int*   t = (const int*)d_in[1];
    const int N = in_sizes[1];

    CLIR_k1_zero_hist<<<CHB, CHT>>>(t, N);
    CLIR_k2_scan<<<1, 128>>>();
    CLIR_k3_scatter<<<CHB, CHT>>>(t, N);
    CLIR_k4_accum<<<A4_BLOCKS, A4_THREADS>>>(x, N);
    CLIR_k5_finalize<<<1, DIM>>>((float*)d_out);
}